// round 12
// baseline (speedup 1.0000x reference)
#include <cuda_runtime.h>
#include <cuda_fp16.h>
#include <cstdint>
#include <math.h>

typedef unsigned int u32;

// Problem constants
#define NB   8192          // batch
#define NCD  512
#define NF   1024
#define NH   8
#define NHD  128

// ---------------- scratch (device globals: no runtime allocation) ----------------
__device__ u32   g_combined_pre_h[(2u * NB * NF) / 2]; // fp16 pre-LN
__device__ u32   g_combined_h[(2u * NB * NF) / 2];     // fp16 post-LN
__device__ u32   g_qkv_h[(2u * NB * 3u * NF) / 2];     // fp16 qkv
__device__ u32   g_attno_h[(2u * NB * NF) / 2];        // fp16 attention output
__device__ u32   g_attnout_h[(2u * NB * NF) / 2];      // fp16 (gate GEMM input view [8192,2048])
__device__ u32   g_gateh_h[((size_t)NB * NF) / 2];     // fp16 gate hidden
__device__ u32   g_fusedpre_h[((size_t)NB * NF) / 2];  // fp16
// fp16 copies of raw inputs
__device__ u32 g_cnn_e_h[((size_t)NB * NCD) / 2];
__device__ u32 g_gnn_e_h[((size_t)NB * NCD) / 2];
__device__ u32 g_cnn_w_h[((size_t)NF * NCD) / 2];
__device__ u32 g_gnn_w_h[((size_t)NF * NCD) / 2];
__device__ u32 g_attn_in_w_h[(3u * NF * NF) / 2];
__device__ u32 g_attn_out_w_h[((size_t)NF * NF) / 2];
__device__ u32 g_gate_w1_h[(2u * NF * NF) / 2];
__device__ u32 g_proj_w_h[((size_t)NF * NF) / 2];

__device__ __forceinline__ float gelu_exact(float x) {
    return 0.5f * x * (1.0f + erff(x * 0.7071067811865476f));
}

__device__ __forceinline__ void mma_f16(
    float& c0, float& c1, float& c2, float& c3,
    u32 a0, u32 a1, u32 a2, u32 a3, u32 b0, u32 b1)
{
    asm volatile(
        "mma.sync.aligned.m16n8k16.row.col.f32.f16.f16.f32 "
        "{%0,%1,%2,%3}, {%4,%5,%6,%7}, {%8,%9}, {%0,%1,%2,%3};"
        : "+f"(c0), "+f"(c1), "+f"(c2), "+f"(c3)
        : "r"(a0), "r"(a1), "r"(a2), "r"(a3), "r"(b0), "r"(b1));
}

__device__ __forceinline__ void cp16(u32 smem_addr, const void* gptr) {
    asm volatile("cp.async.cg.shared.global [%0], [%1], 16;"
                 :: "r"(smem_addr), "l"(gptr));
}

__device__ __forceinline__ void ldsm4(u32& r0, u32& r1, u32& r2, u32& r3, u32 addr) {
    asm volatile("ldmatrix.sync.aligned.m8n8.x4.shared.b16 {%0,%1,%2,%3}, [%4];"
                 : "=r"(r0), "=r"(r1), "=r"(r2), "=r"(r3) : "r"(addr));
}

__device__ __forceinline__ float4 ld4h(const __half* p) {
    uint2 r = *(const uint2*)p;
    __half2 a = *(__half2*)&r.x, b = *(__half2*)&r.y;
    float2 fa = __half22float2(a), fb = __half22float2(b);
    return make_float4(fa.x, fa.y, fb.x, fb.y);
}

// ---------------------------------------------------------------------------
// fp16 tensor-core GEMM core (fp32 accumulate). C = act( A @ W^T + bias ).
// CTA tile 128x128, 8 warps of 64x32 (2 CTAs/SM). BK=64 halves (row = 128B),
// XOR-16B swizzled smem, 3-stage cp.async pipeline (prefetch distance 2),
// ONE __syncthreads per chunk.
// MODE: 0 = fp32 out C, 1 = fp16 out C2 only, 2 = both.
// Requires M%128==0, N%128==0, K%64==0, K/64 >= 2.
// ---------------------------------------------------------------------------
#define STAGE_B  32768      // A tile 16KB + B tile 16KB
#define GSMEM    (3 * STAGE_B)

template <int ACT, int MODE>
__device__ __forceinline__ void gemm_core(
    const __half* __restrict__ A, const __half* __restrict__ W,
    const float* __restrict__ bias, float* __restrict__ C,
    __half* __restrict__ C2, int K, int ldc, int m0, int n0, u32* sm)
{
    const int tid = threadIdx.x;
    const int wid  = tid >> 5;
    const int lane = tid & 31;
    const int g    = lane >> 2;
    const int tig  = lane & 3;
    const int wm   = (wid >> 2) * 64;
    const int wn   = (wid & 3) * 32;

    const int lr  = tid >> 3;         // 0..31 (row within 32-row slab)
    const int lc8 = tid & 7;          // 16B chunk within 128B row

    const u32 smem_base = (u32)__cvta_generic_to_shared(sm);
    const u32 slot = (u32)(lr * 128 + ((lc8 ^ (lr & 7)) << 4));

    const int t8 = lane >> 3;
    const int r8 = lane & 7;
    u32 arow[4];
#pragma unroll
    for (int mi = 0; mi < 4; mi++)
        arow[mi] = (u32)((wm + mi * 16 + (t8 & 1) * 8 + r8) * 128);
    const u32 acx = (u32)(t8 >> 1);
    u32 brow[2];
    brow[0] = (u32)((wn + (t8 >> 1) * 8 + r8) * 128);
    brow[1] = (u32)((wn + 16 + (t8 >> 1) * 8 + r8) * 128);
    const u32 bcx = (u32)(t8 & 1);
    const u32 rx = (u32)r8;

    const __half* gA = A + (size_t)(m0 + lr) * K + lc8 * 8;
    const __half* gW = W + (size_t)(n0 + lr) * K + lc8 * 8;

    float acc[4][4][4];
#pragma unroll
    for (int i = 0; i < 4; i++)
#pragma unroll
        for (int j = 0; j < 4; j++)
#pragma unroll
            for (int r = 0; r < 4; r++) acc[i][j][r] = 0.0f;

    const int kt = K >> 6;            // 64-half chunks

    auto issue = [&](int t, int s) {
        const int k0 = t << 6;
        const u32 ab = smem_base + (u32)s * STAGE_B + slot;
        const u32 bb = ab + 16384u;
#pragma unroll
        for (int s4 = 0; s4 < 4; s4++) {
            cp16(ab + s4 * 4096, gA + (size_t)s4 * 32 * K + k0);
            cp16(bb + s4 * 4096, gW + (size_t)s4 * 32 * K + k0);
        }
        asm volatile("cp.async.commit_group;");
    };

    issue(0, 0);
    issue(1, 1);

    for (int t = 0; t < kt; t++) {
        if (t < kt - 1) asm volatile("cp.async.wait_group 1;");
        else            asm volatile("cp.async.wait_group 0;");
        __syncthreads();
        if (t + 2 < kt) issue(t + 2, (t + 2) % 3);

        const u32 Abase = smem_base + (u32)(t % 3) * STAGE_B;
        const u32 Bbase = Abase + 16384u;

#pragma unroll
        for (int ks = 0; ks < 4; ks++) {          // 4 x k16 steps
            const u32 kc = (u32)(2 * ks);
            u32 af[4][4];
            u32 bf[2][4];
#pragma unroll
            for (int mi = 0; mi < 4; mi++)
                ldsm4(af[mi][0], af[mi][1], af[mi][2], af[mi][3],
                      Abase + arow[mi] + (((acx + kc) ^ rx) << 4));
#pragma unroll
            for (int p = 0; p < 2; p++)
                ldsm4(bf[p][0], bf[p][1], bf[p][2], bf[p][3],
                      Bbase + brow[p] + (((bcx + kc) ^ rx) << 4));
#pragma unroll
            for (int ni = 0; ni < 4; ni++) {
                const u32 b0 = bf[ni >> 1][(ni & 1) * 2];
                const u32 b1 = bf[ni >> 1][(ni & 1) * 2 + 1];
#pragma unroll
                for (int mi = 0; mi < 4; mi++)
                    mma_f16(acc[mi][ni][0], acc[mi][ni][1],
                            acc[mi][ni][2], acc[mi][ni][3],
                            af[mi][0], af[mi][1], af[mi][2], af[mi][3],
                            b0, b1);
            }
        }
    }

    // ---- epilogue ----
#pragma unroll
    for (int mi = 0; mi < 4; mi++) {
        const int row = m0 + wm + mi * 16 + g;
#pragma unroll
        for (int ni = 0; ni < 4; ni++) {
            const int col = n0 + wn + ni * 8 + tig * 2;
            const float2 bv = *(const float2*)&bias[col];
            float2 v0, v1;
            v0.x = acc[mi][ni][0] + bv.x;
            v0.y = acc[mi][ni][1] + bv.y;
            v1.x = acc[mi][ni][2] + bv.x;
            v1.y = acc[mi][ni][3] + bv.y;
            if (ACT == 1) {
                v0.x = gelu_exact(v0.x); v0.y = gelu_exact(v0.y);
                v1.x = gelu_exact(v1.x); v1.y = gelu_exact(v1.y);
            }
            const size_t o0 = (size_t)row * ldc + col;
            const size_t o1 = (size_t)(row + 8) * ldc + col;
            if (MODE == 0 || MODE == 2) {
                *(float2*)&C[o0] = v0;
                *(float2*)&C[o1] = v1;
            }
            if (MODE == 1 || MODE == 2) {
                *(__half2*)&C2[o0] = __floats2half2_rn(v0.x, v0.y);
                *(__half2*)&C2[o1] = __floats2half2_rn(v1.x, v1.y);
            }
        }
    }
}

// Persistent-tile wrapper: grid.x CTAs loop over ntiles output tiles.
// Tile t -> m0 = (t / nx)*128, n0 = (t % nx)*128.
template <int ACT, int MODE>
__global__ void __launch_bounds__(256, 2) gemm_p(
    const __half* __restrict__ A, const __half* __restrict__ W,
    const float* __restrict__ bias, float* __restrict__ C,
    __half* __restrict__ C2, int K, int ldc, int nx, int ntiles)
{
    extern __shared__ u32 sm[];
    for (int t = blockIdx.x; t < ntiles; t += gridDim.x) {
        if (t != (int)blockIdx.x) __syncthreads();   // stage-0 reuse hazard
        gemm_core<ACT, MODE>(A, W, bias, C, C2, K, ldc,
                             (t / nx) * 128, (t % nx) * 128, sm);
    }
}

// Persistent merged modality GEMMs: tiles [0,nxy) = cnn, [nxy,2*nxy) = gnn.
__global__ void __launch_bounds__(256, 2) gemm_mod_p(
    const __half* __restrict__ A0, const __half* __restrict__ W0, const float* __restrict__ b0,
    const __half* __restrict__ A1, const __half* __restrict__ W1, const float* __restrict__ b1,
    __half* __restrict__ C2, int nx, int nxy, int ntiles)
{
    extern __shared__ u32 sm[];
    for (int t = blockIdx.x; t < ntiles; t += gridDim.x) {
        if (t != (int)blockIdx.x) __syncthreads();
        const int z = t >= nxy;
        const int l = t - z * nxy;
        gemm_core<0, 1>(z ? A1 : A0, z ? W1 : W0, z ? b1 : b0,
                        nullptr, C2 + (size_t)z * NF, NCD, 2 * NF,
                        (l / nx) * 128, (l % nx) * 128, sm);
    }
}

// ---------------------------------------------------------------------------
// Fused fp32 -> fp16 convert over 8 segments (one launch). float4 units.
// ---------------------------------------------------------------------------
__global__ void __launch_bounds__(256) cvt_all_kernel(
    const float4* s0, const float4* s1, const float4* s2, const float4* s3,
    const float4* s4, const float4* s5, const float4* s6, const float4* s7,
    uint2* d0, uint2* d1, uint2* d2, uint2* d3,
    uint2* d4, uint2* d5, uint2* d6, uint2* d7,
    int n0, int n1, int n2, int n3, int n4, int n5, int n6, int n7)
{
    int i = blockIdx.x * blockDim.x + threadIdx.x;
    const float4* s; uint2* d;
    if      (i < n0)                       { s = s0; d = d0; }
    else if ((i -= n0) < n1)               { s = s1; d = d1; }
    else if ((i -= n1) < n2)               { s = s2; d = d2; }
    else if ((i -= n2) < n3)               { s = s3; d = d3; }
    else if ((i -= n3) < n4)               { s = s4; d = d4; }
    else if ((i -= n4) < n5)               { s = s5; d = d5; }
    else if ((i -= n5) < n6)               { s = s6; d = d6; }
    else if ((i -= n6) < n7)               { s = s7; d = d7; }
    else return;
    float4 v = s[i];
    __half2 h0 = __floats2half2_rn(v.x, v.y);
    __half2 h1 = __floats2half2_rn(v.z, v.w);
    uint2 r;
    r.x = *(u32*)&h0;
    r.y = *(u32*)&h1;
    d[i] = r;
}

// ---------------------------------------------------------------------------
// LayerNorm: fp16 in, fp16 out (stats in fp32). Warp-shuffle reduction +
// ONE barrier. Even rows ln1, odd rows ln2.
// ---------------------------------------------------------------------------
__global__ void __launch_bounds__(256) ln_kernel(
    const __half* __restrict__ x, __half* __restrict__ xo,
    const float* __restrict__ g1, const float* __restrict__ b1,
    const float* __restrict__ g2, const float* __restrict__ b2)
{
    const int row = blockIdx.x;
    const int tid = threadIdx.x;
    const int wid = tid >> 5;
    const int lane = tid & 31;
    const float* gv = (row & 1) ? g2 : g1;
    const float* bv = (row & 1) ? b2 : b1;

    float4 v = ld4h(x + (size_t)row * NF + tid * 4);
    float s  = v.x + v.y + v.z + v.w;
    float ss = v.x * v.x + v.y * v.y + v.z * v.z + v.w * v.w;

#pragma unroll
    for (int o = 16; o > 0; o >>= 1) {
        s  += __shfl_xor_sync(0xffffffffu, s, o);
        ss += __shfl_xor_sync(0xffffffffu, ss, o);
    }
    __shared__ float ws[8], wss[8];
    if (lane == 0) { ws[wid] = s; wss[wid] = ss; }
    __syncthreads();
    float tot = 0.f, tot2 = 0.f;
#pragma unroll
    for (int i = 0; i < 8; i++) { tot += ws[i]; tot2 += wss[i]; }

    const float inv_n = 1.0f / (float)NF;
    float mean = tot * inv_n;
    float var  = tot2 * inv_n - mean * mean;
    float rstd = rsqrtf(var + 1e-5f);

    float4 gg = ((const float4*)gv)[tid];
    float4 bb = ((const float4*)bv)[tid];
    __half2 h0 = __floats2half2_rn((v.x - mean) * rstd * gg.x + bb.x,
                                   (v.y - mean) * rstd * gg.y + bb.y);
    __half2 h1 = __floats2half2_rn((v.z - mean) * rstd * gg.z + bb.z,
                                   (v.w - mean) * rstd * gg.w + bb.w);
    uint2 o;
    o.x = *(u32*)&h0;
    o.y = *(u32*)&h1;
    ((uint2*)(xo + (size_t)row * NF))[tid] = o;
}

// ---------------------------------------------------------------------------
// Attention (seq 2) per (b,h): one warp. fp16 in/out; math in fp32.
// ---------------------------------------------------------------------------
__global__ void __launch_bounds__(256) attn_kernel(
    const __half* __restrict__ qkv, __half* __restrict__ o)
{
    const int gwarp = (blockIdx.x * blockDim.x + threadIdx.x) >> 5;
    const int lane = threadIdx.x & 31;
    const int b = gwarp >> 3;
    const int h = gwarp & 7;

    const __half* base0 = qkv + (size_t)(2 * b) * 3072 + h * 128 + lane * 4;
    const __half* base1 = base0 + 3072;
    float4 q0 = ld4h(base0);
    float4 k0 = ld4h(base0 + 1024);
    float4 v0 = ld4h(base0 + 2048);
    float4 q1 = ld4h(base1);
    float4 k1 = ld4h(base1 + 1024);
    float4 v1 = ld4h(base1 + 2048);

    float s00 = q0.x * k0.x + q0.y * k0.y + q0.z * k0.z + q0.w * k0.w;
    float s01 = q0.x * k1.x + q0.y * k1.y + q0.z * k1.z + q0.w * k1.w;
    float s10 = q1.x * k0.x + q1.y * k0.y + q1.z * k0.z + q1.w * k0.w;
    float s11 = q1.x * k1.x + q1.y * k1.y + q1.z * k1.z + q1.w * k1.w;
#pragma unroll
    for (int off = 16; off > 0; off >>= 1) {
        s00 += __shfl_xor_sync(0xffffffffu, s00, off);
        s01 += __shfl_xor_sync(0xffffffffu, s01, off);
        s10 += __shfl_xor_sync(0xffffffffu, s10, off);
        s11 += __shfl_xor_sync(0xffffffffu, s11, off);
    }
    const float sc = 0.08838834764831845f;   // 1/sqrt(128)
    s00 *= sc; s01 *= sc; s10 *= sc; s11 *= sc;

    float m0 = fmaxf(s00, s01);
    float e00 = expf(s00 - m0), e01 = expf(s01 - m0);
    float i0 = 1.0f / (e00 + e01);
    float a00 = e00 * i0, a01 = e01 * i0;

    float m1 = fmaxf(s10, s11);
    float e10 = expf(s10 - m1), e11 = expf(s11 - m1);
    float i1 = 1.0f / (e10 + e11);
    float a10 = e10 * i1, a11 = e11 * i1;

    __half2 p00 = __floats2half2_rn(a00 * v0.x + a01 * v1.x, a00 * v0.y + a01 * v1.y);
    __half2 p01 = __floats2half2_rn(a00 * v0.z + a01 * v1.z, a00 * v0.w + a01 * v1.w);
    __half2 p10 = __floats2half2_rn(a10 * v0.x + a11 * v1.x, a10 * v0.y + a11 * v1.y);
    __half2 p11 = __floats2half2_rn(a10 * v0.z + a11 * v1.z, a10 * v0.w + a11 * v1.w);

    __half* obase = o + (size_t)(2 * b) * NF + h * 128 + lane * 4;
    uint2 w0, w1;
    w0.x = *(u32*)&p00; w0.y = *(u32*)&p01;
    w1.x = *(u32*)&p10; w1.y = *(u32*)&p11;
    *(uint2*)(obase) = w0;
    *(uint2*)(obase + NF) = w1;
}

// ---------------------------------------------------------------------------
// gate2 logits + softmax + fused mix. gateh + attnout read fp16; fusedpre fp16.
// ---------------------------------------------------------------------------
__global__ void __launch_bounds__(256) gate_fuse_kernel(
    const __half* __restrict__ gh, const float* __restrict__ w2,
    const float* __restrict__ b2, const __half* __restrict__ attnout_h,
    __half* __restrict__ fusedpre, float* __restrict__ gwout)
{
    const int b = blockIdx.x;
    const int tid = threadIdx.x;
    const int wid = tid >> 5;
    const int lane = tid & 31;

    const float4* w20 = (const float4*)w2;
    const float4* w21 = (const float4*)(w2 + NF);

    float4 hv = ld4h(gh + (size_t)b * NF + tid * 4);
    float4 a = w20[tid];
    float4 c = w21[tid];
    float z0 = hv.x * a.x + hv.y * a.y + hv.z * a.z + hv.w * a.w;
    float z1 = hv.x * c.x + hv.y * c.y + hv.z * c.z + hv.w * c.w;

#pragma unroll
    for (int o = 16; o > 0; o >>= 1) {
        z0 += __shfl_xor_sync(0xffffffffu, z0, o);
        z1 += __shfl_xor_sync(0xffffffffu, z1, o);
    }
    __shared__ float ws[8], wss[8];
    if (lane == 0) { ws[wid] = z0; wss[wid] = z1; }
    __syncthreads();
    float t0 = b2[0], t1 = b2[1];
#pragma unroll
    for (int i = 0; i < 8; i++) { t0 += ws[i]; t1 += wss[i]; }

    float mm = fmaxf(t0, t1);
    float e0 = expf(t0 - mm), e1 = expf(t1 - mm);
    float inv = 1.0f / (e0 + e1);
    float gw0 = e0 * inv, gw1 = e1 * inv;

    if (tid == 0) { gwout[2 * b] = gw0; gwout[2 * b + 1] = gw1; }

    const __half* cb = attnout_h + (size_t)(2 * b) * NF;
    float4 cv = ld4h(cb + tid * 4);
    float4 gv = ld4h(cb + NF + tid * 4);
    __half2 f0 = __floats2half2_rn(gw0 * cv.x + gw1 * gv.x, gw0 * cv.y + gw1 * gv.y);
    __half2 f1 = __floats2half2_rn(gw0 * cv.z + gw1 * gv.z, gw0 * cv.w + gw1 * gv.w);
    uint2 fo;
    fo.x = *(u32*)&f0; fo.y = *(u32*)&f1;
    ((uint2*)(fusedpre + (size_t)b * NF))[tid] = fo;
}

// ---------------------------------------------------------------------------
extern "C" void kernel_launch(void* const* d_in, const int* in_sizes, int n_in,
                              void* d_out, int out_size)
{
    const float* cnn_embed  = (const float*)d_in[0];
    const float* gnn_embed  = (const float*)d_in[1];
    const float* cnn_w      = (const float*)d_in[2];
    const float* cnn_b      = (const float*)d_in[3];
    const float* gnn_w      = (const float*)d_in[4];
    const float* gnn_b      = (const float*)d_in[5];
    const float* ln1_g      = (const float*)d_in[6];
    const float* ln1_b      = (const float*)d_in[7];
    const float* ln2_g      = (const float*)d_in[8];
    const float* ln2_b      = (const float*)d_in[9];
    const float* attn_in_w  = (const float*)d_in[10];
    const float* attn_in_b  = (const float*)d_in[11];
    const float* attn_out_w = (const float*)d_in[12];
    const float* attn_out_b = (const float*)d_in[13];
    const float* gate_w1    = (const float*)d_in[14];
    const float* gate_b1    = (const float*)d_in[15];
    const float* gate_w2    = (const float*)d_in[16];
    const float* gate_b2    = (const float*)d_in[17];
    const float* proj_w     = (const float*)d_in[18];
    const float* proj_b     = (const float*)d_in[19];

    float* out = (float*)d_out;
    float* out_gw = out + (size_t)NB * NF;

    __half *combined_pre_h, *combined_h, *qkv_h, *attno_h, *attnout_h, *gateh_h, *fusedpre_h;
    __half *cnn_e_h, *gnn_e_h, *cnn_w_h, *gnn_w_h, *attn_in_w_h, *attn_out_w_h, *gate_w1_h, *proj_w_h;
    cudaGetSymbolAddress((void**)&combined_pre_h, g_combined_pre_h);
    cudaGetSymbolAddress((void**)&combined_h,   g_combined_h);
    cudaGetSymbolAddress((void**)&qkv_h,        g_qkv_h);
    cudaGetSymbolAddress((void**)&attno_h,      g_attno_h);
    cudaGetSymbolAddress((void**)&attnout_h,    g_attnout_h);
    cudaGetSymbolAddress((void**)&gateh_h,      g_gateh_h);
    cudaGetSymbolAddress((void**)&fusedpre_h,   g_fusedpre_h);
    cudaGetSymbolAddress((void**)&cnn_e_h,      g_cnn_e_h);
    cudaGetSymbolAddress((void**)&gnn_e_h,      g_gnn_e_h);
    cudaGetSymbolAddress((void**)&cnn_w_h,      g_cnn_w_h);
    cudaGetSymbolAddress((void**)&gnn_w_h,      g_gnn_w_h);
    cudaGetSymbolAddress((void**)&attn_in_w_h,  g_attn_in_w_h);
    cudaGetSymbolAddress((void**)&attn_out_w_h, g_attn_out_w_h);
    cudaGetSymbolAddress((void**)&gate_w1_h,    g_gate_w1_h);
    cudaGetSymbolAddress((void**)&proj_w_h,     g_proj_w_h);

    static int nsm = 0;
    static int smem_set = 0;
    if (!smem_set) {
        cudaFuncSetAttribute(gemm_p<0, 1>, cudaFuncAttributeMaxDynamicSharedMemorySize, GSMEM);
        cudaFuncSetAttribute(gemm_p<1, 1>, cudaFuncAttributeMaxDynamicSharedMemorySize, GSMEM);
        cudaFuncSetAttribute(gemm_p<1, 0>, cudaFuncAttributeMaxDynamicSharedMemorySize, GSMEM);
        cudaFuncSetAttribute(gemm_mod_p,   cudaFuncAttributeMaxDynamicSharedMemorySize, GSMEM);
        cudaDeviceGetAttribute(&nsm, cudaDevAttrMultiProcessorCount, 0);
        smem_set = 1;
    }
    const int P = 2 * nsm;   // persistent CTAs (2 per SM)
    auto grid = [&](int ntiles) { return ntiles < P ? ntiles : P; };

    // 0) fused fp32 -> fp16 convert of all raw inputs (single launch)
    const int c0 = (int)((size_t)NB * NCD / 4);       // cnn_embed
    const int c1 = (int)((size_t)NB * NCD / 4);       // gnn_embed
    const int c2 = (int)((size_t)NF * NCD / 4);       // cnn_w
    const int c3 = (int)((size_t)NF * NCD / 4);       // gnn_w
    const int c4 = (int)((size_t)3 * NF * NF / 4);    // attn_in_w
    const int c5 = (int)((size_t)NF * NF / 4);        // attn_out_w
    const int c6 = (int)((size_t)2 * NF * NF / 4);    // gate_w1
    const int c7 = (int)((size_t)NF * NF / 4);        // proj_w
    const int ctot = c0 + c1 + c2 + c3 + c4 + c5 + c6 + c7;
    cvt_all_kernel<<<(ctot + 255) / 256, 256>>>(
        (const float4*)cnn_embed, (const float4*)gnn_embed,
        (const float4*)cnn_w, (const float4*)gnn_w,
        (const float4*)attn_in_w, (const float4*)attn_out_w,
        (const float4*)gate_w1, (const float4*)proj_w,
        (uint2*)cnn_e_h, (uint2*)gnn_e_h, (uint2*)cnn_w_h, (uint2*)gnn_w_h,
        (uint2*)attn_in_w_h, (uint2*)attn_out_w_h, (uint2*)gate_w1_h, (uint2*)proj_w_h,
        c0, c1, c2, c3, c4, c5, c6, c7);

    // 1) merged modality GEMMs -> fp16 combined_pre_h, interleaved rows (ldc=2048)
    gemm_mod_p<<<grid(1024), 256, GSMEM>>>(
        cnn_e_h, cnn_w_h, cnn_b, gnn_e_h, gnn_w_h, gnn_b, combined_pre_h,
        NF / 128, (NF / 128) * (NB / 128), 2 * (NF / 128) * (NB / 128));
    // 2) LayerNorm (fp16 in/out)
    ln_kernel<<<2 * NB, 256>>>(combined_pre_h, combined_h, ln1_g, ln1_b, ln2_g, ln2_b);
    // 3) qkv GEMM -> fp16 qkv_h
    gemm_p<0, 1><<<grid(3072), 256, GSMEM>>>(
        combined_h, attn_in_w_h, attn_in_b, nullptr, qkv_h, NF, 3 * NF,
        3 * NF / 128, (3 * NF / 128) * (2 * NB / 128));
    // 4) attention (fp16 in/out)
    attn_kernel<<<(NB * NH) / 8, 256>>>(qkv_h, attno_h);
    // 5) attn_out GEMM -> fp16
    gemm_p<0, 1><<<grid(1024), 256, GSMEM>>>(
        attno_h, attn_out_w_h, attn_out_b, nullptr, attnout_h, NF, NF,
        NF / 128, (NF / 128) * (2 * NB / 128));
    // 6) gate_h = gelu(gate_in @ gate_w1.T + b) -> fp16; gate_in = attnout_h [8192,2048]
    gemm_p<1, 1><<<grid(512), 256, GSMEM>>>(
        attnout_h, gate_w1_h, gate_b1, nullptr, gateh_h, 2 * NF, NF,
        NF / 128, (NF / 128) * (NB / 128));
    // 7) gate softmax + fused mix (fp16 in, fp16 fusedpre, gate weights out)
    gate_fuse_kernel<<<NB, 256>>>(gateh_h, gate_w2, gate_b2, attnout_h, fusedpre_h, out_gw);
    // 8) fused = gelu(fusedpre @ proj_w.T + proj_b) -> fp32 output
    gemm_p<1, 0><<<grid(512), 256, GSMEM>>>(
        fusedpre_h, proj_w_h, proj_b, out, nullptr, NF, NF,
        NF / 128, (NF / 128) * (NB / 128));
}

// round 14
// speedup vs baseline: 1.0824x; 1.0824x over previous
#include <cuda_runtime.h>
#include <cuda_fp16.h>
#include <cstdint>
#include <math.h>

typedef unsigned int u32;

// Problem constants
#define NB   8192          // batch
#define NCD  512
#define NF   1024
#define NH   8
#define NHD  128

// ---------------- scratch (device globals: no runtime allocation) ----------------
__device__ u32   g_combined_pre_h[(2u * NB * NF) / 2]; // fp16 pre-LN
__device__ u32   g_combined_h[(2u * NB * NF) / 2];     // fp16 post-LN
__device__ u32   g_qkv_h[(2u * NB * 3u * NF) / 2];     // fp16 qkv
__device__ u32   g_attno_h[(2u * NB * NF) / 2];        // fp16 attention output
__device__ u32   g_attnout_h[(2u * NB * NF) / 2];      // fp16 (gate GEMM input view [8192,2048])
__device__ u32   g_gateh_h[((size_t)NB * NF) / 2];     // fp16 gate hidden
__device__ u32   g_fusedpre_h[((size_t)NB * NF) / 2];  // fp16
// fp16 copies of raw inputs
__device__ u32 g_cnn_e_h[((size_t)NB * NCD) / 2];
__device__ u32 g_gnn_e_h[((size_t)NB * NCD) / 2];
__device__ u32 g_cnn_w_h[((size_t)NF * NCD) / 2];
__device__ u32 g_gnn_w_h[((size_t)NF * NCD) / 2];
__device__ u32 g_attn_in_w_h[(3u * NF * NF) / 2];
__device__ u32 g_attn_out_w_h[((size_t)NF * NF) / 2];
__device__ u32 g_gate_w1_h[(2u * NF * NF) / 2];
__device__ u32 g_proj_w_h[((size_t)NF * NF) / 2];

__device__ __forceinline__ float gelu_exact(float x) {
    return 0.5f * x * (1.0f + erff(x * 0.7071067811865476f));
}

__device__ __forceinline__ void mma_f16(
    float& c0, float& c1, float& c2, float& c3,
    u32 a0, u32 a1, u32 a2, u32 a3, u32 b0, u32 b1)
{
    asm volatile(
        "mma.sync.aligned.m16n8k16.row.col.f32.f16.f16.f32 "
        "{%0,%1,%2,%3}, {%4,%5,%6,%7}, {%8,%9}, {%0,%1,%2,%3};"
        : "+f"(c0), "+f"(c1), "+f"(c2), "+f"(c3)
        : "r"(a0), "r"(a1), "r"(a2), "r"(a3), "r"(b0), "r"(b1));
}

__device__ __forceinline__ void cp16(u32 smem_addr, const void* gptr) {
    asm volatile("cp.async.cg.shared.global [%0], [%1], 16;"
                 :: "r"(smem_addr), "l"(gptr));
}

__device__ __forceinline__ void ldsm4(u32& r0, u32& r1, u32& r2, u32& r3, u32 addr) {
    asm volatile("ldmatrix.sync.aligned.m8n8.x4.shared.b16 {%0,%1,%2,%3}, [%4];"
                 : "=r"(r0), "=r"(r1), "=r"(r2), "=r"(r3) : "r"(addr));
}

__device__ __forceinline__ float4 ld4h(const __half* p) {
    uint2 r = *(const uint2*)p;
    __half2 a = *(__half2*)&r.x, b = *(__half2*)&r.y;
    float2 fa = __half22float2(a), fb = __half22float2(b);
    return make_float4(fa.x, fa.y, fb.x, fb.y);
}

// ---------------------------------------------------------------------------
// fp16 tensor-core GEMM core (fp32 accumulate). C = act( A @ W^T + bias ).
// CTA tile 128x128, 8 warps of 64x32 (2 CTAs/SM). BK=64 halves (row = 128B),
// XOR-16B swizzled smem, 3-stage cp.async pipeline (prefetch distance 2),
// ONE __syncthreads per chunk, order: wait(t) -> sync -> issue(t+2) -> compute.
// MODE: 0 = fp32 out C, 1 = fp16 out C2 only, 2 = both.
// Requires M%128==0, N%128==0, K%64==0, K/64 >= 2.
// ---------------------------------------------------------------------------
#define STAGE_B  32768      // A tile 16KB + B tile 16KB
#define GSMEM    (3 * STAGE_B)

template <int ACT, int MODE>
__device__ __forceinline__ void gemm_core(
    const __half* __restrict__ A, const __half* __restrict__ W,
    const float* __restrict__ bias, float* __restrict__ C,
    __half* __restrict__ C2, int K, int ldc, int m0, int n0, u32* sm)
{
    const int tid = threadIdx.x;
    const int wid  = tid >> 5;
    const int lane = tid & 31;
    const int g    = lane >> 2;
    const int tig  = lane & 3;
    const int wm   = (wid >> 2) * 64;
    const int wn   = (wid & 3) * 32;

    const int lr  = tid >> 3;         // 0..31 (row within 32-row slab)
    const int lc8 = tid & 7;          // 16B chunk within 128B row

    const u32 smem_base = (u32)__cvta_generic_to_shared(sm);
    const u32 slot = (u32)(lr * 128 + ((lc8 ^ (lr & 7)) << 4));

    const int t8 = lane >> 3;
    const int r8 = lane & 7;
    u32 arow[4];
#pragma unroll
    for (int mi = 0; mi < 4; mi++)
        arow[mi] = (u32)((wm + mi * 16 + (t8 & 1) * 8 + r8) * 128);
    const u32 acx = (u32)(t8 >> 1);
    u32 brow[2];
    brow[0] = (u32)((wn + (t8 >> 1) * 8 + r8) * 128);
    brow[1] = (u32)((wn + 16 + (t8 >> 1) * 8 + r8) * 128);
    const u32 bcx = (u32)(t8 & 1);
    const u32 rx = (u32)r8;

    const __half* gA = A + (size_t)(m0 + lr) * K + lc8 * 8;
    const __half* gW = W + (size_t)(n0 + lr) * K + lc8 * 8;

    float acc[4][4][4];
#pragma unroll
    for (int i = 0; i < 4; i++)
#pragma unroll
        for (int j = 0; j < 4; j++)
#pragma unroll
            for (int r = 0; r < 4; r++) acc[i][j][r] = 0.0f;

    const int kt = K >> 6;            // 64-half chunks

    auto issue = [&](int t, int s) {
        const int k0 = t << 6;
        const u32 ab = smem_base + (u32)s * STAGE_B + slot;
        const u32 bb = ab + 16384u;
#pragma unroll
        for (int s4 = 0; s4 < 4; s4++) {
            cp16(ab + s4 * 4096, gA + (size_t)s4 * 32 * K + k0);
            cp16(bb + s4 * 4096, gW + (size_t)s4 * 32 * K + k0);
        }
        asm volatile("cp.async.commit_group;");
    };

    issue(0, 0);
    issue(1, 1);

    for (int t = 0; t < kt; t++) {
        if (t < kt - 1) asm volatile("cp.async.wait_group 1;");
        else            asm volatile("cp.async.wait_group 0;");
        __syncthreads();
        if (t + 2 < kt) issue(t + 2, (t + 2) % 3);

        const u32 Abase = smem_base + (u32)(t % 3) * STAGE_B;
        const u32 Bbase = Abase + 16384u;

#pragma unroll
        for (int ks = 0; ks < 4; ks++) {          // 4 x k16 steps
            const u32 kc = (u32)(2 * ks);
            u32 af[4][4];
            u32 bf[2][4];
#pragma unroll
            for (int mi = 0; mi < 4; mi++)
                ldsm4(af[mi][0], af[mi][1], af[mi][2], af[mi][3],
                      Abase + arow[mi] + (((acx + kc) ^ rx) << 4));
#pragma unroll
            for (int p = 0; p < 2; p++)
                ldsm4(bf[p][0], bf[p][1], bf[p][2], bf[p][3],
                      Bbase + brow[p] + (((bcx + kc) ^ rx) << 4));
#pragma unroll
            for (int ni = 0; ni < 4; ni++) {
                const u32 b0 = bf[ni >> 1][(ni & 1) * 2];
                const u32 b1 = bf[ni >> 1][(ni & 1) * 2 + 1];
#pragma unroll
                for (int mi = 0; mi < 4; mi++)
                    mma_f16(acc[mi][ni][0], acc[mi][ni][1],
                            acc[mi][ni][2], acc[mi][ni][3],
                            af[mi][0], af[mi][1], af[mi][2], af[mi][3],
                            b0, b1);
            }
        }
    }

    // ---- epilogue ----
#pragma unroll
    for (int mi = 0; mi < 4; mi++) {
        const int row = m0 + wm + mi * 16 + g;
#pragma unroll
        for (int ni = 0; ni < 4; ni++) {
            const int col = n0 + wn + ni * 8 + tig * 2;
            const float2 bv = *(const float2*)&bias[col];
            float2 v0, v1;
            v0.x = acc[mi][ni][0] + bv.x;
            v0.y = acc[mi][ni][1] + bv.y;
            v1.x = acc[mi][ni][2] + bv.x;
            v1.y = acc[mi][ni][3] + bv.y;
            if (ACT == 1) {
                v0.x = gelu_exact(v0.x); v0.y = gelu_exact(v0.y);
                v1.x = gelu_exact(v1.x); v1.y = gelu_exact(v1.y);
            }
            const size_t o0 = (size_t)row * ldc + col;
            const size_t o1 = (size_t)(row + 8) * ldc + col;
            if (MODE == 0 || MODE == 2) {
                *(float2*)&C[o0] = v0;
                *(float2*)&C[o1] = v1;
            }
            if (MODE == 1 || MODE == 2) {
                *(__half2*)&C2[o0] = __floats2half2_rn(v0.x, v0.y);
                *(__half2*)&C2[o1] = __floats2half2_rn(v1.x, v1.y);
            }
        }
    }
}

template <int ACT, int MODE>
__global__ void __launch_bounds__(256, 2) gemm_h(
    const __half* __restrict__ A, const __half* __restrict__ W,
    const float* __restrict__ bias, float* __restrict__ C,
    __half* __restrict__ C2, int K, int ldc)
{
    extern __shared__ u32 sm[];
    gemm_core<ACT, MODE>(A, W, bias, C, C2, K, ldc,
                         blockIdx.y * 128, blockIdx.x * 128, sm);
}

// Merged modality GEMMs: blockIdx.z selects (cnn, gnn); fp16 out, interleaved rows.
__global__ void __launch_bounds__(256, 2) gemm_mod(
    const __half* __restrict__ A0, const __half* __restrict__ W0, const float* __restrict__ b0,
    const __half* __restrict__ A1, const __half* __restrict__ W1, const float* __restrict__ b1,
    __half* __restrict__ C2)
{
    extern __shared__ u32 sm[];
    const int z = blockIdx.z;
    gemm_core<0, 1>(z ? A1 : A0, z ? W1 : W0, z ? b1 : b0,
                    nullptr, C2 + (size_t)z * NF, NCD, 2 * NF,
                    blockIdx.y * 128, blockIdx.x * 128, sm);
}

// ---------------------------------------------------------------------------
// Fused fp32 -> fp16 convert over 8 segments (one launch). float4 units.
// ---------------------------------------------------------------------------
__global__ void __launch_bounds__(256) cvt_all_kernel(
    const float4* s0, const float4* s1, const float4* s2, const float4* s3,
    const float4* s4, const float4* s5, const float4* s6, const float4* s7,
    uint2* d0, uint2* d1, uint2* d2, uint2* d3,
    uint2* d4, uint2* d5, uint2* d6, uint2* d7,
    int n0, int n1, int n2, int n3, int n4, int n5, int n6, int n7)
{
    int i = blockIdx.x * blockDim.x + threadIdx.x;
    const float4* s; uint2* d;
    if      (i < n0)                       { s = s0; d = d0; }
    else if ((i -= n0) < n1)               { s = s1; d = d1; }
    else if ((i -= n1) < n2)               { s = s2; d = d2; }
    else if ((i -= n2) < n3)               { s = s3; d = d3; }
    else if ((i -= n3) < n4)               { s = s4; d = d4; }
    else if ((i -= n4) < n5)               { s = s5; d = d5; }
    else if ((i -= n5) < n6)               { s = s6; d = d6; }
    else if ((i -= n6) < n7)               { s = s7; d = d7; }
    else return;
    float4 v = s[i];
    __half2 h0 = __floats2half2_rn(v.x, v.y);
    __half2 h1 = __floats2half2_rn(v.z, v.w);
    uint2 r;
    r.x = *(u32*)&h0;
    r.y = *(u32*)&h1;
    d[i] = r;
}

// ---------------------------------------------------------------------------
// LayerNorm: fp16 in, fp16 out (stats in fp32). Warp-shuffle reduction +
// ONE barrier. Even rows ln1, odd rows ln2.
// ---------------------------------------------------------------------------
__global__ void __launch_bounds__(256) ln_kernel(
    const __half* __restrict__ x, __half* __restrict__ xo,
    const float* __restrict__ g1, const float* __restrict__ b1,
    const float* __restrict__ g2, const float* __restrict__ b2)
{
    const int row = blockIdx.x;
    const int tid = threadIdx.x;
    const int wid = tid >> 5;
    const int lane = tid & 31;
    const float* gv = (row & 1) ? g2 : g1;
    const float* bv = (row & 1) ? b2 : b1;

    float4 v = ld4h(x + (size_t)row * NF + tid * 4);
    float s  = v.x + v.y + v.z + v.w;
    float ss = v.x * v.x + v.y * v.y + v.z * v.z + v.w * v.w;

#pragma unroll
    for (int o = 16; o > 0; o >>= 1) {
        s  += __shfl_xor_sync(0xffffffffu, s, o);
        ss += __shfl_xor_sync(0xffffffffu, ss, o);
    }
    __shared__ float ws[8], wss[8];
    if (lane == 0) { ws[wid] = s; wss[wid] = ss; }
    __syncthreads();
    float tot = 0.f, tot2 = 0.f;
#pragma unroll
    for (int i = 0; i < 8; i++) { tot += ws[i]; tot2 += wss[i]; }

    const float inv_n = 1.0f / (float)NF;
    float mean = tot * inv_n;
    float var  = tot2 * inv_n - mean * mean;
    float rstd = rsqrtf(var + 1e-5f);

    float4 gg = ((const float4*)gv)[tid];
    float4 bb = ((const float4*)bv)[tid];
    __half2 h0 = __floats2half2_rn((v.x - mean) * rstd * gg.x + bb.x,
                                   (v.y - mean) * rstd * gg.y + bb.y);
    __half2 h1 = __floats2half2_rn((v.z - mean) * rstd * gg.z + bb.z,
                                   (v.w - mean) * rstd * gg.w + bb.w);
    uint2 o;
    o.x = *(u32*)&h0;
    o.y = *(u32*)&h1;
    ((uint2*)(xo + (size_t)row * NF))[tid] = o;
}

// ---------------------------------------------------------------------------
// Attention (seq 2) per (b,h): one warp. fp16 in/out; math in fp32.
// ---------------------------------------------------------------------------
__global__ void __launch_bounds__(256) attn_kernel(
    const __half* __restrict__ qkv, __half* __restrict__ o)
{
    const int gwarp = (blockIdx.x * blockDim.x + threadIdx.x) >> 5;
    const int lane = threadIdx.x & 31;
    const int b = gwarp >> 3;
    const int h = gwarp & 7;

    const __half* base0 = qkv + (size_t)(2 * b) * 3072 + h * 128 + lane * 4;
    const __half* base1 = base0 + 3072;
    float4 q0 = ld4h(base0);
    float4 k0 = ld4h(base0 + 1024);
    float4 v0 = ld4h(base0 + 2048);
    float4 q1 = ld4h(base1);
    float4 k1 = ld4h(base1 + 1024);
    float4 v1 = ld4h(base1 + 2048);

    float s00 = q0.x * k0.x + q0.y * k0.y + q0.z * k0.z + q0.w * k0.w;
    float s01 = q0.x * k1.x + q0.y * k1.y + q0.z * k1.z + q0.w * k1.w;
    float s10 = q1.x * k0.x + q1.y * k0.y + q1.z * k0.z + q1.w * k0.w;
    float s11 = q1.x * k1.x + q1.y * k1.y + q1.z * k1.z + q1.w * k1.w;
#pragma unroll
    for (int off = 16; off > 0; off >>= 1) {
        s00 += __shfl_xor_sync(0xffffffffu, s00, off);
        s01 += __shfl_xor_sync(0xffffffffu, s01, off);
        s10 += __shfl_xor_sync(0xffffffffu, s10, off);
        s11 += __shfl_xor_sync(0xffffffffu, s11, off);
    }
    const float sc = 0.08838834764831845f;   // 1/sqrt(128)
    s00 *= sc; s01 *= sc; s10 *= sc; s11 *= sc;

    float m0 = fmaxf(s00, s01);
    float e00 = expf(s00 - m0), e01 = expf(s01 - m0);
    float i0 = 1.0f / (e00 + e01);
    float a00 = e00 * i0, a01 = e01 * i0;

    float m1 = fmaxf(s10, s11);
    float e10 = expf(s10 - m1), e11 = expf(s11 - m1);
    float i1 = 1.0f / (e10 + e11);
    float a10 = e10 * i1, a11 = e11 * i1;

    __half2 p00 = __floats2half2_rn(a00 * v0.x + a01 * v1.x, a00 * v0.y + a01 * v1.y);
    __half2 p01 = __floats2half2_rn(a00 * v0.z + a01 * v1.z, a00 * v0.w + a01 * v1.w);
    __half2 p10 = __floats2half2_rn(a10 * v0.x + a11 * v1.x, a10 * v0.y + a11 * v1.y);
    __half2 p11 = __floats2half2_rn(a10 * v0.z + a11 * v1.z, a10 * v0.w + a11 * v1.w);

    __half* obase = o + (size_t)(2 * b) * NF + h * 128 + lane * 4;
    uint2 w0, w1;
    w0.x = *(u32*)&p00; w0.y = *(u32*)&p01;
    w1.x = *(u32*)&p10; w1.y = *(u32*)&p11;
    *(uint2*)(obase) = w0;
    *(uint2*)(obase + NF) = w1;
}

// ---------------------------------------------------------------------------
// gate2 logits + softmax + fused mix. gateh + attnout read fp16; fusedpre fp16.
// ---------------------------------------------------------------------------
__global__ void __launch_bounds__(256) gate_fuse_kernel(
    const __half* __restrict__ gh, const float* __restrict__ w2,
    const float* __restrict__ b2, const __half* __restrict__ attnout_h,
    __half* __restrict__ fusedpre, float* __restrict__ gwout)
{
    const int b = blockIdx.x;
    const int tid = threadIdx.x;
    const int wid = tid >> 5;
    const int lane = tid & 31;

    const float4* w20 = (const float4*)w2;
    const float4* w21 = (const float4*)(w2 + NF);

    float4 hv = ld4h(gh + (size_t)b * NF + tid * 4);
    float4 a = w20[tid];
    float4 c = w21[tid];
    float z0 = hv.x * a.x + hv.y * a.y + hv.z * a.z + hv.w * a.w;
    float z1 = hv.x * c.x + hv.y * c.y + hv.z * c.z + hv.w * c.w;

#pragma unroll
    for (int o = 16; o > 0; o >>= 1) {
        z0 += __shfl_xor_sync(0xffffffffu, z0, o);
        z1 += __shfl_xor_sync(0xffffffffu, z1, o);
    }
    __shared__ float ws[8], wss[8];
    if (lane == 0) { ws[wid] = z0; wss[wid] = z1; }
    __syncthreads();
    float t0 = b2[0], t1 = b2[1];
#pragma unroll
    for (int i = 0; i < 8; i++) { t0 += ws[i]; t1 += wss[i]; }

    float mm = fmaxf(t0, t1);
    float e0 = expf(t0 - mm), e1 = expf(t1 - mm);
    float inv = 1.0f / (e0 + e1);
    float gw0 = e0 * inv, gw1 = e1 * inv;

    if (tid == 0) { gwout[2 * b] = gw0; gwout[2 * b + 1] = gw1; }

    const __half* cb = attnout_h + (size_t)(2 * b) * NF;
    float4 cv = ld4h(cb + tid * 4);
    float4 gv = ld4h(cb + NF + tid * 4);
    __half2 f0 = __floats2half2_rn(gw0 * cv.x + gw1 * gv.x, gw0 * cv.y + gw1 * gv.y);
    __half2 f1 = __floats2half2_rn(gw0 * cv.z + gw1 * gv.z, gw0 * cv.w + gw1 * gv.w);
    uint2 fo;
    fo.x = *(u32*)&f0; fo.y = *(u32*)&f1;
    ((uint2*)(fusedpre + (size_t)b * NF))[tid] = fo;
}

// ---------------------------------------------------------------------------
extern "C" void kernel_launch(void* const* d_in, const int* in_sizes, int n_in,
                              void* d_out, int out_size)
{
    const float* cnn_embed  = (const float*)d_in[0];
    const float* gnn_embed  = (const float*)d_in[1];
    const float* cnn_w      = (const float*)d_in[2];
    const float* cnn_b      = (const float*)d_in[3];
    const float* gnn_w      = (const float*)d_in[4];
    const float* gnn_b      = (const float*)d_in[5];
    const float* ln1_g      = (const float*)d_in[6];
    const float* ln1_b      = (const float*)d_in[7];
    const float* ln2_g      = (const float*)d_in[8];
    const float* ln2_b      = (const float*)d_in[9];
    const float* attn_in_w  = (const float*)d_in[10];
    const float* attn_in_b  = (const float*)d_in[11];
    const float* attn_out_w = (const float*)d_in[12];
    const float* attn_out_b = (const float*)d_in[13];
    const float* gate_w1    = (const float*)d_in[14];
    const float* gate_b1    = (const float*)d_in[15];
    const float* gate_w2    = (const float*)d_in[16];
    const float* gate_b2    = (const float*)d_in[17];
    const float* proj_w     = (const float*)d_in[18];
    const float* proj_b     = (const float*)d_in[19];

    float* out = (float*)d_out;
    float* out_gw = out + (size_t)NB * NF;

    __half *combined_pre_h, *combined_h, *qkv_h, *attno_h, *attnout_h, *gateh_h, *fusedpre_h;
    __half *cnn_e_h, *gnn_e_h, *cnn_w_h, *gnn_w_h, *attn_in_w_h, *attn_out_w_h, *gate_w1_h, *proj_w_h;
    cudaGetSymbolAddress((void**)&combined_pre_h, g_combined_pre_h);
    cudaGetSymbolAddress((void**)&combined_h,   g_combined_h);
    cudaGetSymbolAddress((void**)&qkv_h,        g_qkv_h);
    cudaGetSymbolAddress((void**)&attno_h,      g_attno_h);
    cudaGetSymbolAddress((void**)&attnout_h,    g_attnout_h);
    cudaGetSymbolAddress((void**)&gateh_h,      g_gateh_h);
    cudaGetSymbolAddress((void**)&fusedpre_h,   g_fusedpre_h);
    cudaGetSymbolAddress((void**)&cnn_e_h,      g_cnn_e_h);
    cudaGetSymbolAddress((void**)&gnn_e_h,      g_gnn_e_h);
    cudaGetSymbolAddress((void**)&cnn_w_h,      g_cnn_w_h);
    cudaGetSymbolAddress((void**)&gnn_w_h,      g_gnn_w_h);
    cudaGetSymbolAddress((void**)&attn_in_w_h,  g_attn_in_w_h);
    cudaGetSymbolAddress((void**)&attn_out_w_h, g_attn_out_w_h);
    cudaGetSymbolAddress((void**)&gate_w1_h,    g_gate_w1_h);
    cudaGetSymbolAddress((void**)&proj_w_h,     g_proj_w_h);

    static int smem_set = 0;
    if (!smem_set) {
        cudaFuncSetAttribute(gemm_h<0, 1>, cudaFuncAttributeMaxDynamicSharedMemorySize, GSMEM);
        cudaFuncSetAttribute(gemm_h<1, 1>, cudaFuncAttributeMaxDynamicSharedMemorySize, GSMEM);
        cudaFuncSetAttribute(gemm_h<1, 0>, cudaFuncAttributeMaxDynamicSharedMemorySize, GSMEM);
        cudaFuncSetAttribute(gemm_mod,     cudaFuncAttributeMaxDynamicSharedMemorySize, GSMEM);
        smem_set = 1;
    }

    // 0) fused fp32 -> fp16 convert of all raw inputs (single launch)
    const int c0 = (int)((size_t)NB * NCD / 4);       // cnn_embed
    const int c1 = (int)((size_t)NB * NCD / 4);       // gnn_embed
    const int c2 = (int)((size_t)NF * NCD / 4);       // cnn_w
    const int c3 = (int)((size_t)NF * NCD / 4);       // gnn_w
    const int c4 = (int)((size_t)3 * NF * NF / 4);    // attn_in_w
    const int c5 = (int)((size_t)NF * NF / 4);        // attn_out_w
    const int c6 = (int)((size_t)2 * NF * NF / 4);    // gate_w1
    const int c7 = (int)((size_t)NF * NF / 4);        // proj_w
    const int ctot = c0 + c1 + c2 + c3 + c4 + c5 + c6 + c7;
    cvt_all_kernel<<<(ctot + 255) / 256, 256>>>(
        (const float4*)cnn_embed, (const float4*)gnn_embed,
        (const float4*)cnn_w, (const float4*)gnn_w,
        (const float4*)attn_in_w, (const float4*)attn_out_w,
        (const float4*)gate_w1, (const float4*)proj_w,
        (uint2*)cnn_e_h, (uint2*)gnn_e_h, (uint2*)cnn_w_h, (uint2*)gnn_w_h,
        (uint2*)attn_in_w_h, (uint2*)attn_out_w_h, (uint2*)gate_w1_h, (uint2*)proj_w_h,
        c0, c1, c2, c3, c4, c5, c6, c7);

    // 1) merged modality GEMMs -> fp16 combined_pre_h, interleaved rows (ldc=2048)
    gemm_mod<<<dim3(NF / 128, NB / 128, 2), 256, GSMEM>>>(
        cnn_e_h, cnn_w_h, cnn_b, gnn_e_h, gnn_w_h, gnn_b, combined_pre_h);
    // 2) LayerNorm (fp16 in/out)
    ln_kernel<<<2 * NB, 256>>>(combined_pre_h, combined_h, ln1_g, ln1_b, ln2_g, ln2_b);
    // 3) qkv GEMM -> fp16 qkv_h
    gemm_h<0, 1><<<dim3(3 * NF / 128, 2 * NB / 128), 256, GSMEM>>>(
        combined_h, attn_in_w_h, attn_in_b, nullptr, qkv_h, NF, 3 * NF);
    // 4) attention (fp16 in/out)
    attn_kernel<<<(NB * NH) / 8, 256>>>(qkv_h, attno_h);
    // 5) attn_out GEMM -> fp16
    gemm_h<0, 1><<<dim3(NF / 128, 2 * NB / 128), 256, GSMEM>>>(
        attno_h, attn_out_w_h, attn_out_b, nullptr, attnout_h, NF, NF);
    // 6) gate_h = gelu(gate_in @ gate_w1.T + b) -> fp16; gate_in = attnout_h [8192,2048]
    gemm_h<1, 1><<<dim3(NF / 128, NB / 128), 256, GSMEM>>>(
        attnout_h, gate_w1_h, gate_b1, nullptr, gateh_h, 2 * NF, NF);
    // 7) gate softmax + fused mix (fp16 in, fp16 fusedpre, gate weights out)
    gate_fuse_kernel<<<NB, 256>>>(gateh_h, gate_w2, gate_b2, attnout_h, fusedpre_h, out_gw);
    // 8) fused = gelu(fusedpre @ proj_w.T + proj_b) -> fp32 output
    gemm_h<1, 0><<<dim3(NF / 128, NB / 128), 256, GSMEM>>>(
        fusedpre_h, proj_w_h, proj_b, out, nullptr, NF, NF);
}